// round 2
// baseline (speedup 1.0000x reference)
#include <cuda_runtime.h>
#include <cstdint>

#define NN 100000
#define NE 1600000
#define NG 1000
#define F  100
#define FC 25   // float4 chunks per feature row

// ---------------- scratch (device globals: allowed) ----------------
__device__ __align__(16) float g_xw[NN * F];     // h @ W
__device__ __align__(16) float g_agg[NN * F];    // scattered aggregate
__device__ __align__(16) float g_h[NN * F];      // layer output
__device__ float g_deg[NN];
__device__ float g_dinv[NN];
__device__ float g_selfw[NN];      // 2/deg
__device__ int   g_row[NE];
__device__ int   g_col[NE];
__device__ int   g_batch[NN];
__device__ float g_ew[NE];         // dinv[row]*dinv[col]
__device__ __align__(16) float g_pool[NG * F];
__device__ float g_cnt[NG];
__device__ float g_t1[NG * F];
__device__ float g_t2[NG * F];
__device__ int   g_is64;           // 1 if index inputs are int64, 0 if int32

__device__ __forceinline__ void red4(float4* p, float x, float y, float z, float w) {
    asm volatile("red.global.add.v4.f32 [%0], {%1,%2,%3,%4};"
                 :: "l"(p), "f"(x), "f"(y), "f"(z), "f"(w) : "memory");
}

// ---------------- dtype detection ----------------
// If edge_index is int64 (values < 2^31, nonneg), every odd int32 word is 0.
// If it is int32 (random values in [0,100000)), odd words are index values
// and the OR over 1024 of them is nonzero with probability ~1.
__global__ void detect_kernel(const int* __restrict__ ei32) {
    __shared__ int s;
    if (threadIdx.x == 0) s = 0;
    __syncthreads();
    int v = ei32[threadIdx.x * 2 + 1] | ei32[2048 + threadIdx.x * 2 + 1] |
            ei32[4096 + threadIdx.x * 2 + 1] | ei32[6144 + threadIdx.x * 2 + 1];
    if (v) atomicOr(&s, 1);
    __syncthreads();
    if (threadIdx.x == 0) g_is64 = (s == 0) ? 1 : 0;
}

// ---------------- preprocessing ----------------
__global__ void prep_edges_kernel(const void* __restrict__ ei) {
    int e = blockIdx.x * blockDim.x + threadIdx.x;
    if (e >= NE) return;
    if (g_is64) {
        const long long* p = (const long long*)ei;
        g_row[e] = (int)p[e];
        g_col[e] = (int)p[NE + e];
    } else {
        const int* p = (const int*)ei;
        g_row[e] = p[e];
        g_col[e] = p[NE + e];
    }
}

__global__ void prep_batch_kernel(const void* __restrict__ batch) {
    int i = blockIdx.x * blockDim.x + threadIdx.x;
    if (i >= NN) return;
    if (g_is64) g_batch[i] = (int)((const long long*)batch)[i];
    else        g_batch[i] = ((const int*)batch)[i];
}

__global__ void zero_deg_kernel() {
    int i = blockIdx.x * blockDim.x + threadIdx.x;
    if (i < NN) g_deg[i] = 0.0f;
}

__global__ void deg_kernel() {
    int e = blockIdx.x * blockDim.x + threadIdx.x;
    if (e < NE) atomicAdd(&g_deg[g_col[e]], 1.0f);
}

__global__ void dinv_kernel() {
    int i = blockIdx.x * blockDim.x + threadIdx.x;
    if (i < NN) {
        float d = g_deg[i] + 2.0f;
        float r = rsqrtf(d);
        r = r * (1.5f - 0.5f * d * r * r);   // Newton refine
        g_dinv[i]  = r;
        g_selfw[i] = 2.0f / d;
    }
}

__global__ void ew_kernel() {
    int e = blockIdx.x * blockDim.x + threadIdx.x;
    if (e < NE) g_ew[e] = g_dinv[g_row[e]] * g_dinv[g_col[e]];
}

// ---------------- SGEMM: g_xw = A[M,K] @ W[K,100] ----------------
__global__ __launch_bounds__(256) void sgemm_kernel(
    const float* __restrict__ Aext, const float* __restrict__ Wt,
    int useH, int M, int K)
{
    const float* A = useH ? g_h : Aext;
    __shared__ float As[8][128];
    __shared__ float Bs[8][128];
    int t  = threadIdx.x;
    int m0 = blockIdx.y * 128;

    int arow = t >> 1;            // 0..127
    int acol = (t & 1) << 2;      // 0 or 4  (along K)
    int brow = t >> 5;            // 0..7    (along K)
    int bcol = (t & 31) << 2;     // 0..124  (along N)
    int tx = t & 15, ty = t >> 4;
    int tn0 = tx * 8;
    int tm0 = ty * 8;

    float acc[8][8];
#pragma unroll
    for (int i = 0; i < 8; i++)
#pragma unroll
        for (int j = 0; j < 8; j++) acc[i][j] = 0.0f;

    for (int k0 = 0; k0 < K; k0 += 8) {
        float4 av = make_float4(0.f, 0.f, 0.f, 0.f);
        {
            int gm = m0 + arow;
            int gk = k0 + acol;
            if (gm < M && gk < K)
                av = *(const float4*)(A + (size_t)gm * K + gk);
        }
        As[acol + 0][arow] = av.x;
        As[acol + 1][arow] = av.y;
        As[acol + 2][arow] = av.z;
        As[acol + 3][arow] = av.w;

        float4 bv = make_float4(0.f, 0.f, 0.f, 0.f);
        {
            int gk = k0 + brow;
            if (gk < K && bcol < 100)
                bv = *(const float4*)(Wt + (size_t)gk * 100 + bcol);
        }
        *(float4*)&Bs[brow][bcol] = bv;

        __syncthreads();
#pragma unroll
        for (int k = 0; k < 8; k++) {
            float rm[8], rn[8];
            *(float4*)&rm[0] = *(const float4*)&As[k][tm0];
            *(float4*)&rm[4] = *(const float4*)&As[k][tm0 + 4];
            *(float4*)&rn[0] = *(const float4*)&Bs[k][tn0];
            *(float4*)&rn[4] = *(const float4*)&Bs[k][tn0 + 4];
#pragma unroll
            for (int i = 0; i < 8; i++)
#pragma unroll
                for (int j = 0; j < 8; j++)
                    acc[i][j] = fmaf(rm[i], rn[j], acc[i][j]);
        }
        __syncthreads();
    }

#pragma unroll
    for (int i = 0; i < 8; i++) {
        int gm = m0 + tm0 + i;
        if (gm >= M) continue;
#pragma unroll
        for (int j = 0; j < 8; j++) {
            int gn = tn0 + j;
            if (gn < 100) g_xw[(size_t)gm * 100 + gn] = acc[i][j];
        }
    }
}

// ---------------- per-layer aggregation ----------------
__global__ void zero_agg_kernel() {
    int idx = blockIdx.x * blockDim.x + threadIdx.x;
    if (idx < NN * FC) ((float4*)g_agg)[idx] = make_float4(0.f, 0.f, 0.f, 0.f);
}

__global__ void scatter_kernel() {
    int idx = blockIdx.x * blockDim.x + threadIdx.x;   // edge*25 + chunk
    if (idx >= NE * FC) return;
    int e  = idx / FC;
    int ch = idx - e * FC;
    int r = g_row[e];
    int c = g_col[e];
    float wt = g_ew[e];
    float4 v = ((const float4*)g_xw)[r * FC + ch];
    red4(((float4*)g_agg) + (c * FC + ch), v.x * wt, v.y * wt, v.z * wt, v.w * wt);
}

__global__ void finalize_kernel(const float* __restrict__ bias) {
    int idx = blockIdx.x * blockDim.x + threadIdx.x;
    if (idx >= NN * FC) return;
    int i  = idx / FC;
    int ch = idx - i * FC;
    float sw = g_selfw[i];
    float4 a  = ((const float4*)g_agg)[idx];
    float4 xv = ((const float4*)g_xw)[idx];
    float4 b  = __ldg(((const float4*)bias) + ch);
    float4 o;
    o.x = fmaxf(fmaf(sw, xv.x, a.x) + b.x, 0.f);
    o.y = fmaxf(fmaf(sw, xv.y, a.y) + b.y, 0.f);
    o.z = fmaxf(fmaf(sw, xv.z, a.z) + b.z, 0.f);
    o.w = fmaxf(fmaf(sw, xv.w, a.w) + b.w, 0.f);
    ((float4*)g_h)[idx] = o;
}

// ---------------- pooling ----------------
__global__ void zero_pool_kernel() {
    int idx = blockIdx.x * blockDim.x + threadIdx.x;
    if (idx < NG * FC) ((float4*)g_pool)[idx] = make_float4(0.f, 0.f, 0.f, 0.f);
    if (idx < NG) g_cnt[idx] = 0.0f;
}

__global__ void cnt_kernel() {
    int i = blockIdx.x * blockDim.x + threadIdx.x;
    if (i < NN) atomicAdd(&g_cnt[g_batch[i]], 1.0f);
}

__global__ void pool_kernel() {
    int idx = blockIdx.x * blockDim.x + threadIdx.x;
    if (idx >= NN * FC) return;
    int i  = idx / FC;
    int ch = idx - i * FC;
    int g = g_batch[i];
    float4 v = ((const float4*)g_h)[idx];
    red4(((float4*)g_pool) + (g * FC + ch), v.x, v.y, v.z, v.w);
}

__global__ void pooldiv_kernel() {
    int idx = blockIdx.x * blockDim.x + threadIdx.x;
    if (idx >= NG * F) return;
    int g = idx / F;
    g_pool[idx] = g_pool[idx] / fmaxf(g_cnt[g], 1.0f);
}

// ---------------- MLP head ----------------
__global__ void mlp_kernel(const float* __restrict__ Wt, const float* __restrict__ bias,
                           float* __restrict__ outp, int stage, int Kd, int Nd, int doRelu)
{
    const float* A = (stage == 0) ? g_pool : (stage == 1) ? g_t1 : g_t2;
    float*       C = (stage == 0) ? g_t1   : (stage == 1) ? g_t2 : outp;
    __shared__ float arow[128];
    int g = blockIdx.x, j = threadIdx.x;
    if (j < Kd) arow[j] = A[g * Kd + j];
    __syncthreads();
    if (j < Nd) {
        float s = bias[j];
        for (int k = 0; k < Kd; k++) s = fmaf(arow[k], Wt[k * Nd + j], s);
        if (doRelu) s = fmaxf(s, 0.f);
        C[g * Nd + j] = s;
    }
}

// ---------------- launch ----------------
extern "C" void kernel_launch(void* const* d_in, const int* in_sizes, int n_in,
                              void* d_out, int out_size)
{
    const float* x     = (const float*)d_in[0];
    const void*  ei    = d_in[1];
    const void*  batch = d_in[2];
    const float* Wc[5] = {(const float*)d_in[3], (const float*)d_in[5], (const float*)d_in[7],
                          (const float*)d_in[9], (const float*)d_in[11]};
    const float* Bc[5] = {(const float*)d_in[4], (const float*)d_in[6], (const float*)d_in[8],
                          (const float*)d_in[10], (const float*)d_in[12]};
    const float* Wl1 = (const float*)d_in[13];
    const float* bl1 = (const float*)d_in[14];
    const float* Wl2 = (const float*)d_in[15];
    const float* bl2 = (const float*)d_in[16];
    const float* Wl3 = (const float*)d_in[17];
    const float* bl3 = (const float*)d_in[18];
    float* out = (float*)d_out;

    const int TB = 256;

    // dtype probe + edge preprocessing + normalization
    detect_kernel<<<1, 512>>>((const int*)ei);
    prep_edges_kernel<<<(NE + TB - 1) / TB, TB>>>(ei);
    prep_batch_kernel<<<(NN + TB - 1) / TB, TB>>>(batch);
    zero_deg_kernel<<<(NN + TB - 1) / TB, TB>>>();
    deg_kernel<<<(NE + TB - 1) / TB, TB>>>();
    dinv_kernel<<<(NN + TB - 1) / TB, TB>>>();
    ew_kernel<<<(NE + TB - 1) / TB, TB>>>();

    // 5 GCN layers
    int K = 336;
    int useH = 0;
    for (int l = 0; l < 5; l++) {
        dim3 grid(1, (NN + 127) / 128);
        sgemm_kernel<<<grid, 256>>>(x, Wc[l], useH, NN, K);
        zero_agg_kernel<<<(NN * FC + TB - 1) / TB, TB>>>();
        scatter_kernel<<<(NE * FC + TB - 1) / TB, TB>>>();
        finalize_kernel<<<(NN * FC + TB - 1) / TB, TB>>>(Bc[l]);
        K = 100;
        useH = 1;
    }

    // global mean pool
    zero_pool_kernel<<<(NG * FC + TB - 1) / TB, TB>>>();
    cnt_kernel<<<(NN + TB - 1) / TB, TB>>>();
    pool_kernel<<<(NN * FC + TB - 1) / TB, TB>>>();
    pooldiv_kernel<<<(NG * F + TB - 1) / TB, TB>>>();

    // MLP head
    mlp_kernel<<<NG, 128>>>(Wl1, bl1, nullptr, 0, 100, 100, 1);
    mlp_kernel<<<NG, 128>>>(Wl2, bl2, nullptr, 1, 100, 100, 1);
    mlp_kernel<<<NG, 128>>>(Wl3, bl3, out, 2, 100, 29, 0);
}

// round 3
// speedup vs baseline: 1.3343x; 1.3343x over previous
#include <cuda_runtime.h>
#include <cstdint>

#define NN 100000
#define NE 1600000
#define NG 1000
#define F  100
#define FC 25   // float4 chunks per feature row

// ---------------- scratch (device globals: allowed) ----------------
__device__ __align__(16) float g_xw[NN * F];     // h @ W
__device__ __align__(16) float g_h[NN * F];      // layer output
__device__ int   g_degi[NN];
__device__ int   g_off[NN + 1];
__device__ int   g_cur[NN];
__device__ float g_dinv[NN];
__device__ float g_selfw[NN];      // 2/deg
__device__ int   g_row[NE];
__device__ int   g_col[NE];
__device__ int   g_src[NE];        // CSR: source node per in-edge (sorted by dst)
__device__ float g_wt[NE];         // CSR: edge weight dinv[src]*dinv[dst]
__device__ int   g_batch[NN];
__device__ __align__(16) float g_pool[NG * F];
__device__ float g_cnt[NG];
__device__ float g_t1[NG * F];
__device__ float g_t2[NG * F];
__device__ int   g_is64;           // 1 if index inputs are int64, 0 if int32

__device__ __forceinline__ void red4(float4* p, float x, float y, float z, float w) {
    asm volatile("red.global.add.v4.f32 [%0], {%1,%2,%3,%4};"
                 :: "l"(p), "f"(x), "f"(y), "f"(z), "f"(w) : "memory");
}

// ---------------- dtype detection ----------------
__global__ void detect_kernel(const int* __restrict__ ei32) {
    __shared__ int s;
    if (threadIdx.x == 0) s = 0;
    __syncthreads();
    int v = ei32[threadIdx.x * 2 + 1] | ei32[2048 + threadIdx.x * 2 + 1] |
            ei32[4096 + threadIdx.x * 2 + 1] | ei32[6144 + threadIdx.x * 2 + 1];
    if (v) atomicOr(&s, 1);
    __syncthreads();
    if (threadIdx.x == 0) g_is64 = (s == 0) ? 1 : 0;
}

// ---------------- preprocessing ----------------
__global__ void zero_degi_kernel() {
    int i = blockIdx.x * blockDim.x + threadIdx.x;
    if (i < NN) g_degi[i] = 0;
}

// parse edge index + count in-degree in one pass
__global__ void prep_deg_kernel(const void* __restrict__ ei) {
    int e = blockIdx.x * blockDim.x + threadIdx.x;
    if (e >= NE) return;
    int r, c;
    if (g_is64) {
        const long long* p = (const long long*)ei;
        r = (int)p[e];
        c = (int)p[NE + e];
    } else {
        const int* p = (const int*)ei;
        r = p[e];
        c = p[NE + e];
    }
    g_row[e] = r;
    g_col[e] = c;
    atomicAdd(&g_degi[c], 1);
}

__global__ void prep_batch_kernel(const void* __restrict__ batch) {
    int i = blockIdx.x * blockDim.x + threadIdx.x;
    if (i >= NN) return;
    if (g_is64) g_batch[i] = (int)((const long long*)batch)[i];
    else        g_batch[i] = ((const int*)batch)[i];
}

// single-block exclusive scan of g_degi -> g_off, g_cur
__global__ void scan_kernel() {
    __shared__ int ssum[1024];
    const int T = 1024;
    int t = threadIdx.x;
    const int per = (NN + T - 1) / T;   // 98
    int base = t * per;
    int s = 0;
    for (int i = 0; i < per; i++) {
        int idx = base + i;
        if (idx < NN) s += g_degi[idx];
    }
    ssum[t] = s;
    __syncthreads();
    for (int off = 1; off < T; off <<= 1) {
        int v = (t >= off) ? ssum[t - off] : 0;
        __syncthreads();
        ssum[t] += v;
        __syncthreads();
    }
    int run = ssum[t] - s;   // exclusive prefix for this thread's chunk
    for (int i = 0; i < per; i++) {
        int idx = base + i;
        if (idx < NN) {
            g_off[idx] = run;
            g_cur[idx] = run;
            run += g_degi[idx];
        }
    }
    if (t == T - 1) g_off[NN] = run;
}

__global__ void dinv_kernel() {
    int i = blockIdx.x * blockDim.x + threadIdx.x;
    if (i < NN) {
        float d = (float)g_degi[i] + 2.0f;
        float r = rsqrtf(d);
        r = r * (1.5f - 0.5f * d * r * r);   // Newton refine
        g_dinv[i]  = r;
        g_selfw[i] = 2.0f / d;
    }
}

// counting-sort edges into CSR, compute weight inline
__global__ void fill_kernel() {
    int e = blockIdx.x * blockDim.x + threadIdx.x;
    if (e >= NE) return;
    int r = g_row[e];
    int c = g_col[e];
    int pos = atomicAdd(&g_cur[c], 1);
    g_src[pos] = r;
    g_wt[pos]  = g_dinv[r] * g_dinv[c];
}

// ---------------- SGEMM: g_xw = A[M,K] @ W[K,100] ----------------
__global__ __launch_bounds__(256) void sgemm_kernel(
    const float* __restrict__ Aext, const float* __restrict__ Wt,
    int useH, int M, int K)
{
    const float* A = useH ? g_h : Aext;
    __shared__ float As[8][128];
    __shared__ float Bs[8][128];
    int t  = threadIdx.x;
    int m0 = blockIdx.y * 128;

    int arow = t >> 1;            // 0..127
    int acol = (t & 1) << 2;      // 0 or 4  (along K)
    int brow = t >> 5;            // 0..7    (along K)
    int bcol = (t & 31) << 2;     // 0..124  (along N)
    int tx = t & 15, ty = t >> 4;
    int tn0 = tx * 8;
    int tm0 = ty * 8;

    float acc[8][8];
#pragma unroll
    for (int i = 0; i < 8; i++)
#pragma unroll
        for (int j = 0; j < 8; j++) acc[i][j] = 0.0f;

    for (int k0 = 0; k0 < K; k0 += 8) {
        float4 av = make_float4(0.f, 0.f, 0.f, 0.f);
        {
            int gm = m0 + arow;
            int gk = k0 + acol;
            if (gm < M && gk < K)
                av = *(const float4*)(A + (size_t)gm * K + gk);
        }
        As[acol + 0][arow] = av.x;
        As[acol + 1][arow] = av.y;
        As[acol + 2][arow] = av.z;
        As[acol + 3][arow] = av.w;

        float4 bv = make_float4(0.f, 0.f, 0.f, 0.f);
        {
            int gk = k0 + brow;
            if (gk < K && bcol < 100)
                bv = *(const float4*)(Wt + (size_t)gk * 100 + bcol);
        }
        *(float4*)&Bs[brow][bcol] = bv;

        __syncthreads();
#pragma unroll
        for (int k = 0; k < 8; k++) {
            float rm[8], rn[8];
            *(float4*)&rm[0] = *(const float4*)&As[k][tm0];
            *(float4*)&rm[4] = *(const float4*)&As[k][tm0 + 4];
            *(float4*)&rn[0] = *(const float4*)&Bs[k][tn0];
            *(float4*)&rn[4] = *(const float4*)&Bs[k][tn0 + 4];
#pragma unroll
            for (int i = 0; i < 8; i++)
#pragma unroll
                for (int j = 0; j < 8; j++)
                    acc[i][j] = fmaf(rm[i], rn[j], acc[i][j]);
        }
        __syncthreads();
    }

#pragma unroll
    for (int i = 0; i < 8; i++) {
        int gm = m0 + tm0 + i;
        if (gm >= M) continue;
#pragma unroll
        for (int j = 0; j < 8; j++) {
            int gn = tn0 + j;
            if (gn < 100) g_xw[(size_t)gm * 100 + gn] = acc[i][j];
        }
    }
}

// ---------------- fused GCN aggregation (CSR pull) ----------------
// one warp per node; lanes 0..24 each own one float4 feature chunk
__global__ __launch_bounds__(256) void gather_kernel(const float* __restrict__ bias) {
    int node = blockIdx.x * 8 + (threadIdx.x >> 5);
    int lane = threadIdx.x & 31;
    if (node >= NN || lane >= FC) return;
    int beg = g_off[node];
    int end = g_off[node + 1];
    const float4* xw4 = (const float4*)g_xw;

    float4 acc = make_float4(0.f, 0.f, 0.f, 0.f);
    int j = beg;
    for (; j + 1 < end; j += 2) {
        int   r0 = __ldg(&g_src[j]);
        float w0 = __ldg(&g_wt[j]);
        int   r1 = __ldg(&g_src[j + 1]);
        float w1 = __ldg(&g_wt[j + 1]);
        float4 v0 = xw4[r0 * FC + lane];
        float4 v1 = xw4[r1 * FC + lane];
        acc.x = fmaf(w0, v0.x, acc.x); acc.y = fmaf(w0, v0.y, acc.y);
        acc.z = fmaf(w0, v0.z, acc.z); acc.w = fmaf(w0, v0.w, acc.w);
        acc.x = fmaf(w1, v1.x, acc.x); acc.y = fmaf(w1, v1.y, acc.y);
        acc.z = fmaf(w1, v1.z, acc.z); acc.w = fmaf(w1, v1.w, acc.w);
    }
    if (j < end) {
        int   r0 = __ldg(&g_src[j]);
        float w0 = __ldg(&g_wt[j]);
        float4 v0 = xw4[r0 * FC + lane];
        acc.x = fmaf(w0, v0.x, acc.x); acc.y = fmaf(w0, v0.y, acc.y);
        acc.z = fmaf(w0, v0.z, acc.z); acc.w = fmaf(w0, v0.w, acc.w);
    }

    float sw = g_selfw[node];
    float4 xv = xw4[node * FC + lane];
    float4 b  = __ldg(((const float4*)bias) + lane);
    float4 o;
    o.x = fmaxf(fmaf(sw, xv.x, acc.x) + b.x, 0.f);
    o.y = fmaxf(fmaf(sw, xv.y, acc.y) + b.y, 0.f);
    o.z = fmaxf(fmaf(sw, xv.z, acc.z) + b.z, 0.f);
    o.w = fmaxf(fmaf(sw, xv.w, acc.w) + b.w, 0.f);
    ((float4*)g_h)[node * FC + lane] = o;
}

// ---------------- pooling ----------------
__global__ void zero_pool_kernel() {
    int idx = blockIdx.x * blockDim.x + threadIdx.x;
    if (idx < NG * FC) ((float4*)g_pool)[idx] = make_float4(0.f, 0.f, 0.f, 0.f);
    if (idx < NG) g_cnt[idx] = 0.0f;
}

__global__ void cnt_kernel() {
    int i = blockIdx.x * blockDim.x + threadIdx.x;
    if (i < NN) atomicAdd(&g_cnt[g_batch[i]], 1.0f);
}

__global__ void pool_kernel() {
    int idx = blockIdx.x * blockDim.x + threadIdx.x;
    if (idx >= NN * FC) return;
    int i  = idx / FC;
    int ch = idx - i * FC;
    int g = g_batch[i];
    float4 v = ((const float4*)g_h)[idx];
    red4(((float4*)g_pool) + (g * FC + ch), v.x, v.y, v.z, v.w);
}

__global__ void pooldiv_kernel() {
    int idx = blockIdx.x * blockDim.x + threadIdx.x;
    if (idx >= NG * F) return;
    int g = idx / F;
    g_pool[idx] = g_pool[idx] / fmaxf(g_cnt[g], 1.0f);
}

// ---------------- MLP head ----------------
__global__ void mlp_kernel(const float* __restrict__ Wt, const float* __restrict__ bias,
                           float* __restrict__ outp, int stage, int Kd, int Nd, int doRelu)
{
    const float* A = (stage == 0) ? g_pool : (stage == 1) ? g_t1 : g_t2;
    float*       C = (stage == 0) ? g_t1   : (stage == 1) ? g_t2 : outp;
    __shared__ float arow[128];
    int g = blockIdx.x, j = threadIdx.x;
    if (j < Kd) arow[j] = A[g * Kd + j];
    __syncthreads();
    if (j < Nd) {
        float s = bias[j];
        for (int k = 0; k < Kd; k++) s = fmaf(arow[k], Wt[k * Nd + j], s);
        if (doRelu) s = fmaxf(s, 0.f);
        C[g * Nd + j] = s;
    }
}

// ---------------- launch ----------------
extern "C" void kernel_launch(void* const* d_in, const int* in_sizes, int n_in,
                              void* d_out, int out_size)
{
    const float* x     = (const float*)d_in[0];
    const void*  ei    = d_in[1];
    const void*  batch = d_in[2];
    const float* Wc[5] = {(const float*)d_in[3], (const float*)d_in[5], (const float*)d_in[7],
                          (const float*)d_in[9], (const float*)d_in[11]};
    const float* Bc[5] = {(const float*)d_in[4], (const float*)d_in[6], (const float*)d_in[8],
                          (const float*)d_in[10], (const float*)d_in[12]};
    const float* Wl1 = (const float*)d_in[13];
    const float* bl1 = (const float*)d_in[14];
    const float* Wl2 = (const float*)d_in[15];
    const float* bl2 = (const float*)d_in[16];
    const float* Wl3 = (const float*)d_in[17];
    const float* bl3 = (const float*)d_in[18];
    float* out = (float*)d_out;

    const int TB = 256;

    // dtype probe + CSR construction
    detect_kernel<<<1, 512>>>((const int*)ei);
    zero_degi_kernel<<<(NN + TB - 1) / TB, TB>>>();
    prep_deg_kernel<<<(NE + TB - 1) / TB, TB>>>(ei);
    prep_batch_kernel<<<(NN + TB - 1) / TB, TB>>>(batch);
    scan_kernel<<<1, 1024>>>();
    dinv_kernel<<<(NN + TB - 1) / TB, TB>>>();
    fill_kernel<<<(NE + TB - 1) / TB, TB>>>();

    // 5 GCN layers
    int K = 336;
    int useH = 0;
    for (int l = 0; l < 5; l++) {
        dim3 grid(1, (NN + 127) / 128);
        sgemm_kernel<<<grid, 256>>>(x, Wc[l], useH, NN, K);
        gather_kernel<<<(NN + 7) / 8, 256>>>(Bc[l]);
        K = 100;
        useH = 1;
    }

    // global mean pool
    zero_pool_kernel<<<(NG * FC + TB - 1) / TB, TB>>>();
    cnt_kernel<<<(NN + TB - 1) / TB, TB>>>();
    pool_kernel<<<(NN * FC + TB - 1) / TB, TB>>>();
    pooldiv_kernel<<<(NG * F + TB - 1) / TB, TB>>>();

    // MLP head
    mlp_kernel<<<NG, 128>>>(Wl1, bl1, nullptr, 0, 100, 100, 1);
    mlp_kernel<<<NG, 128>>>(Wl2, bl2, nullptr, 1, 100, 100, 1);
    mlp_kernel<<<NG, 128>>>(Wl3, bl3, out, 2, 100, 29, 0);
}